// round 15
// baseline (speedup 1.0000x reference)
#include <cuda_runtime.h>
#include <math.h>
#include <stdint.h>

#define B_ 2
#define S_ 2048
#define D_ 1024
#define H_ 16
#define M_ (B_*S_)

// Scratch (allocation-free rule: __device__ globals)
__device__ float g_Qp[(size_t)B_*S_*D_];
__device__ float g_Kp[(size_t)B_*S_*D_];   // stored tf32-rounded
__device__ float g_Vp[(size_t)B_*S_*D_];   // stored tf32-rounded
__device__ float g_Att[(size_t)B_*S_*D_];  // stored tf32-rounded (attn epilogue)
// tf32-rounded copies of GEMM operands (pre-pass)
__device__ float g_q32[(size_t)B_*S_*D_];
__device__ float g_k32[(size_t)B_*S_*D_];
__device__ float g_v32[(size_t)B_*S_*D_];
__device__ float g_Wq32[(size_t)D_*D_];
__device__ float g_Wk32[(size_t)D_*D_];
__device__ float g_Wv32[(size_t)D_*D_];
__device__ float g_Wo32[(size_t)D_*D_];

__device__ __forceinline__ uint32_t f2tf32(float x) {
    uint32_t r;
    asm("cvt.rna.tf32.f32 %0, %1;" : "=r"(r) : "f"(x));
    return r;
}

__device__ __forceinline__ void mma_tf32(float* d, const uint32_t* a, const uint32_t* b) {
    asm volatile(
        "mma.sync.aligned.m16n8k8.row.col.f32.tf32.tf32.f32 "
        "{%0,%1,%2,%3}, {%4,%5,%6,%7}, {%8,%9}, {%0,%1,%2,%3};"
        : "+f"(d[0]), "+f"(d[1]), "+f"(d[2]), "+f"(d[3])
        : "r"(a[0]), "r"(a[1]), "r"(a[2]), "r"(a[3]), "r"(b[0]), "r"(b[1]));
}

__device__ __forceinline__ uint32_t smem_u32(const void* p) {
    uint32_t a;
    asm("{ .reg .u64 t; cvta.to.shared.u64 t, %1; cvt.u32.u64 %0, t; }"
        : "=r"(a) : "l"(p));
    return a;
}

__device__ __forceinline__ void cp_async16(uint32_t saddr, const void* g) {
    asm volatile("cp.async.cg.shared.global [%0], [%1], 16;"
                 :: "r"(saddr), "l"(g) : "memory");
}
#define CP_COMMIT()  asm volatile("cp.async.commit_group;" ::: "memory")
#define CP_WAIT(n_)  asm volatile("cp.async.wait_group %0;" :: "n"(n_) : "memory")

// ---------------------------------------------------------------------------
// tf32 pre-rounding pass (bit-identical to rounding at fragment-load time).
// ---------------------------------------------------------------------------
__global__ __launch_bounds__(256) void round_inputs_kernel(
    const float* __restrict__ q, const float* __restrict__ k,
    const float* __restrict__ v)
{
    const float* src = (blockIdx.y == 0) ? q : (blockIdx.y == 1) ? k : v;
    float* dst = (blockIdx.y == 0) ? g_q32 : (blockIdx.y == 1) ? g_k32 : g_v32;
    size_t i = (size_t)blockIdx.x * 256 + threadIdx.x;   // float4 index
    float4 x = ((const float4*)src)[i];
    uint4 r = { f2tf32(x.x), f2tf32(x.y), f2tf32(x.z), f2tf32(x.w) };
    ((uint4*)dst)[i] = r;
}

__global__ __launch_bounds__(256) void round_weights_kernel(
    const float* __restrict__ Wq, const float* __restrict__ Wk,
    const float* __restrict__ Wv, const float* __restrict__ Wo)
{
    const float* src = (blockIdx.y == 0) ? Wq : (blockIdx.y == 1) ? Wk :
                       (blockIdx.y == 2) ? Wv : Wo;
    float* dst = (blockIdx.y == 0) ? g_Wq32 : (blockIdx.y == 1) ? g_Wk32 :
                 (blockIdx.y == 2) ? g_Wv32 : g_Wo32;
    size_t i = (size_t)blockIdx.x * 256 + threadIdx.x;   // float4 index
    float4 x = ((const float4*)src)[i];
    uint4 r = { f2tf32(x.x), f2tf32(x.y), f2tf32(x.z), f2tf32(x.w) };
    ((uint4*)dst)[i] = r;
}

// ---------------------------------------------------------------------------
// tf32 mma.sync GEMM: operands arrive PRE-ROUNDED tf32 -> ZERO cvt in loop
// (fragments feed raw bits to mma; bit-identical to cvt-at-load).
// CTA 128x128, BK=32, 256 threads (8 warps 2x4), 2-stage cp.async.
// ROUND_TF32: round outputs at store (K/V consumed by attention).
// ---------------------------------------------------------------------------
#define GST_ 36
#define GSTAGE_ (128*GST_)

template<int DO_ROPE, int ROUND_TF32>
__device__ __forceinline__ void gemm_mma_body(const float* __restrict__ A,
                                              const float* __restrict__ W,
                                              const float* __restrict__ bias,
                                              float* __restrict__ C)
{
    extern __shared__ float gsm_[];
    float* Asf = gsm_;                    // [2][128][36]
    float* Bsf = gsm_ + 2 * GSTAGE_;      // [2][128][36]

    const int tid  = threadIdx.x;
    const int lane = tid & 31, w = tid >> 5;
    const int warpM = w & 1, warpN = w >> 1;
    const int g = lane >> 2, tg = lane & 3;
    const int m0 = blockIdx.y * 128, n0 = blockIdx.x * 128;

    const uint32_t sA_u = smem_u32(Asf);
    const uint32_t sB_u = smem_u32(Bsf);

    #define ISSUE_STAGE(s_, buf_) do {                                        \
        const int k0_ = (s_) * 32;                                            \
        _Pragma("unroll")                                                     \
        for (int t = 0; t < 4; t++) {                                         \
            int slot = tid + t * 256;                                         \
            int r = slot >> 3, qd = slot & 7;                                 \
            uint32_t so = (uint32_t)(((buf_) * GSTAGE_ + r * GST_ + qd * 4) * 4); \
            cp_async16(sA_u + so, A + (size_t)(m0 + r) * 1024 + k0_ + qd * 4);\
            cp_async16(sB_u + so, W + (size_t)(n0 + r) * 1024 + k0_ + qd * 4);\
        }                                                                     \
    } while (0)

    float acc[4][4][4];
    #pragma unroll
    for (int i = 0; i < 4; i++)
        #pragma unroll
        for (int j = 0; j < 4; j++)
            #pragma unroll
            for (int x = 0; x < 4; x++) acc[i][j][x] = 0.f;

    ISSUE_STAGE(0, 0);
    CP_COMMIT();

    #pragma unroll 1
    for (int s = 0; s < 32; s++) {
        if (s + 1 < 32) {
            ISSUE_STAGE(s + 1, (s + 1) & 1);
            CP_COMMIT();
            CP_WAIT(1);
        } else {
            CP_WAIT(0);
        }
        __syncthreads();

        const uint32_t* Ab = (const uint32_t*)(Asf + (s & 1) * GSTAGE_);
        const uint32_t* Bb = (const uint32_t*)(Bsf + (s & 1) * GSTAGE_);
        #pragma unroll
        for (int ks = 0; ks < 4; ks++) {
            const int kc = ks * 8 + tg;
            uint32_t af[4][4];
            #pragma unroll
            for (int mt = 0; mt < 4; mt++) {
                const uint32_t* p = Ab + (warpM * 64 + mt * 16 + g) * GST_ + kc;
                af[mt][0] = p[0];
                af[mt][1] = p[8 * GST_];
                af[mt][2] = p[4];
                af[mt][3] = p[8 * GST_ + 4];
            }
            uint32_t bf[4][2];
            #pragma unroll
            for (int nt = 0; nt < 4; nt++) {
                const uint32_t* p = Bb + (warpN * 8 + nt * 32 + g) * GST_ + kc;
                bf[nt][0] = p[0];
                bf[nt][1] = p[4];
            }
            #pragma unroll
            for (int mt = 0; mt < 4; mt++)
                #pragma unroll
                for (int nt = 0; nt < 4; nt++)
                    mma_tf32(acc[mt][nt], af[mt], bf[nt]);
        }
        __syncthreads();
    }
    #undef ISSUE_STAGE

    float bcol[4][2];
    #pragma unroll
    for (int nt = 0; nt < 4; nt++) {
        bcol[nt][0] = bias[n0 + warpN * 8 + nt * 32 + 2 * tg + 0];
        bcol[nt][1] = bias[n0 + warpN * 8 + nt * 32 + 2 * tg + 1];
    }
    #pragma unroll
    for (int mt = 0; mt < 4; mt++)
        #pragma unroll
        for (int nt = 0; nt < 4; nt++) {
            acc[mt][nt][0] += bcol[nt][0];
            acc[mt][nt][1] += bcol[nt][1];
            acc[mt][nt][2] += bcol[nt][0];
            acc[mt][nt][3] += bcol[nt][1];
        }

    if (DO_ROPE) {
        float sn[2][8], cs[2][8];
        #pragma unroll
        for (int jj = 0; jj < 2; jj++) {
            int jcol = warpN * 8 + 2 * tg + jj;
            float invf = (float)exp(-(double)jcol * 0.28782313662425574);
            #pragma unroll
            for (int mt = 0; mt < 4; mt++)
                #pragma unroll
                for (int half = 0; half < 2; half++) {
                    int row = m0 + warpM * 64 + mt * 16 + g + 8 * half;
                    float sp = (float)(row & (S_ - 1));
                    sincosf(sp * invf, &sn[jj][mt * 2 + half], &cs[jj][mt * 2 + half]);
                }
        }
        #pragma unroll
        for (int mt = 0; mt < 4; mt++)
            #pragma unroll
            for (int p = 0; p < 2; p++)
                #pragma unroll
                for (int idx = 0; idx < 4; idx++) {
                    int jj = idx & 1, half = idx >> 1;
                    float c = cs[jj][mt * 2 + half], s = sn[jj][mt * 2 + half];
                    float x1 = acc[mt][2 * p][idx], x2 = acc[mt][2 * p + 1][idx];
                    acc[mt][2 * p][idx]     = x1 * c - x2 * s;
                    acc[mt][2 * p + 1][idx] = x1 * s + x2 * c;
                }
    }

    #pragma unroll
    for (int mt = 0; mt < 4; mt++)
        #pragma unroll
        for (int nt = 0; nt < 4; nt++)
            #pragma unroll
            for (int half = 0; half < 2; half++) {
                int row = m0 + warpM * 64 + mt * 16 + g + 8 * half;
                int col = n0 + warpN * 8 + nt * 32 + 2 * tg;
                float2 ov;
                if (ROUND_TF32) {
                    ov.x = __uint_as_float(f2tf32(acc[mt][nt][half * 2]));
                    ov.y = __uint_as_float(f2tf32(acc[mt][nt][half * 2 + 1]));
                } else {
                    ov.x = acc[mt][nt][half * 2];
                    ov.y = acc[mt][nt][half * 2 + 1];
                }
                *(float2*)(C + (size_t)row * 1024 + col) = ov;
            }
}

__global__ __launch_bounds__(256, 2)
void qkv_gemm_mma(const float* __restrict__ bq, const float* __restrict__ bk,
                  const float* __restrict__ bv)
{
    if (blockIdx.z == 0)      gemm_mma_body<1, 0>(g_q32, g_Wq32, bq, g_Qp);
    else if (blockIdx.z == 1) gemm_mma_body<1, 1>(g_k32, g_Wk32, bk, g_Kp);
    else                      gemm_mma_body<0, 1>(g_v32, g_Wv32, bv, g_Vp);
}

__global__ __launch_bounds__(256, 2)
void out_gemm_mma(const float* __restrict__ bo, float* __restrict__ out)
{
    gemm_mma_body<0, 0>(g_Att, g_Wo32, bo, out);
}

// ---------------------------------------------------------------------------
// Causal flash attention (round-12 exact config, best measured):
// K double-buffered prefetch, V shadow-buffered, Ps tf32, Q in registers,
// K/V pre-rounded -> zero cvt in mma loops. Epilogue now rounds g_Att to
// tf32 (bit-identical to out_gemm's former fragment cvt).
// smem = 4*64*68*4 = 69632 B -> 3 CTAs/SM.
// ---------------------------------------------------------------------------
#define AST_ 68
__global__ __launch_bounds__(128, 3) void attn_kernel()
{
    extern __shared__ float afm_[];
    float*    Kraw = afm_;                          // [2][64][68] (tf32 bits)
    float*    Vraw = afm_ + 2 * 64 * AST_;          // [64][68]    (tf32 bits)
    uint32_t* Ps   = (uint32_t*)(afm_ + 3 * 64 * AST_);

    const int tid = threadIdx.x;
    const int lane = tid & 31, w = tid >> 5;
    const int g = lane >> 2, tg = lane & 3;
    const int qt = (int)(gridDim.x - 1) - (int)blockIdx.x;   // heavy first
    const int h = blockIdx.y, b = blockIdx.z;

    const float* Qb = g_Qp + ((size_t)b * S_ + qt * 64) * D_ + h * 64;
    const float* Kb = g_Kp + (size_t)b * S_ * D_ + h * 64;
    const float* Vb = g_Vp + (size_t)b * S_ * D_ + h * 64;

    const uint32_t kraw_u = smem_u32(Kraw);
    const uint32_t vraw_u = smem_u32(Vraw);

    #define ISSUE_K(kt_, buf_) do {                                           \
        _Pragma("unroll")                                                     \
        for (int t = 0; t < 8; t++) {                                         \
            int slot = tid + t * 128;                                         \
            int r = slot >> 4, qd = slot & 15;                                \
            uint32_t so = (uint32_t)((((buf_) * 64 + r) * AST_ + qd * 4) * 4);\
            cp_async16(kraw_u + so, Kb + (size_t)((kt_) * 64 + r) * D_ + qd * 4); \
        }                                                                     \
    } while (0)
    #define ISSUE_V(kt_) do {                                                 \
        _Pragma("unroll")                                                     \
        for (int t = 0; t < 8; t++) {                                         \
            int slot = tid + t * 128;                                         \
            int r = slot >> 4, qd = slot & 15;                                \
            uint32_t so = (uint32_t)((r * AST_ + qd * 4) * 4);                \
            cp_async16(vraw_u + so, Vb + (size_t)((kt_) * 64 + r) * D_ + qd * 4); \
        }                                                                     \
    } while (0)

    ISSUE_K(0, 0); CP_COMMIT();

    // ---- Q a-fragments into registers (scaled 1/8, tf32, kt-invariant) ----
    uint32_t qf[8][4];
    {
        const float* q0 = Qb + (size_t)(w * 16 + g) * D_;
        const float* q1 = Qb + (size_t)(w * 16 + g + 8) * D_;
        #pragma unroll
        for (int ks = 0; ks < 8; ks++) {
            int c = ks * 8 + tg;
            qf[ks][0] = f2tf32(q0[c]     * 0.125f);
            qf[ks][1] = f2tf32(q1[c]     * 0.125f);
            qf[ks][2] = f2tf32(q0[c + 4] * 0.125f);
            qf[ks][3] = f2tf32(q1[c + 4] * 0.125f);
        }
    }

    float m[2], l[2], o[8][4];
    m[0] = m[1] = -INFINITY; l[0] = l[1] = 0.f;
    #pragma unroll
    for (int nt = 0; nt < 8; nt++)
        #pragma unroll
        for (int c = 0; c < 4; c++) o[nt][c] = 0.f;

    #pragma unroll 1
    for (int kt = 0; kt <= qt; kt++) {
        ISSUE_V(kt); CP_COMMIT();
        if (kt + 1 <= qt) {
            ISSUE_K(kt + 1, (kt + 1) & 1); CP_COMMIT();
            CP_WAIT(2);
        } else {
            CP_WAIT(1);
        }
        __syncthreads();

        const uint32_t* KtU = (const uint32_t*)(Kraw + (kt & 1) * 64 * AST_);

        // ---- S = Q K^T (1xTF32; K bits pre-rounded, no cvt) ----
        float sacc[8][4];
        #pragma unroll
        for (int nt = 0; nt < 8; nt++)
            #pragma unroll
            for (int c = 0; c < 4; c++) sacc[nt][c] = 0.f;

        #pragma unroll
        for (int ks = 0; ks < 8; ks++) {
            #pragma unroll
            for (int nt = 0; nt < 8; nt++) {
                const int bbase = (nt * 8 + g) * AST_ + ks * 8 + tg;
                uint32_t bh[2];
                bh[0] = KtU[bbase];
                bh[1] = KtU[bbase + 4];
                mma_tf32(sacc[nt], qf[ks], bh);
            }
        }

        // ---- masking (diag tile only) ----
        if (kt == qt) {
            #pragma unroll
            for (int nt = 0; nt < 8; nt++)
                #pragma unroll
                for (int c = 0; c < 4; c++) {
                    int colL = nt * 8 + 2 * tg + (c & 1);
                    int rowL = w * 16 + g + 8 * (c >> 1);
                    if (colL > rowL) sacc[nt][c] = -INFINITY;
                }
        }

        // ---- online softmax ----
        float rm[2] = {-INFINITY, -INFINITY};
        #pragma unroll
        for (int nt = 0; nt < 8; nt++) {
            rm[0] = fmaxf(rm[0], fmaxf(sacc[nt][0], sacc[nt][1]));
            rm[1] = fmaxf(rm[1], fmaxf(sacc[nt][2], sacc[nt][3]));
        }
        #pragma unroll
        for (int r = 0; r < 2; r++) {
            rm[r] = fmaxf(rm[r], __shfl_xor_sync(0xffffffffu, rm[r], 1));
            rm[r] = fmaxf(rm[r], __shfl_xor_sync(0xffffffffu, rm[r], 2));
        }
        float alpha[2], rs[2];
        #pragma unroll
        for (int r = 0; r < 2; r++) {
            float mn = fmaxf(m[r], rm[r]);
            alpha[r] = __expf(m[r] - mn);
            m[r] = mn;
            rs[r] = 0.f;
        }
        #pragma unroll
        for (int nt = 0; nt < 8; nt++) {
            #pragma unroll
            for (int c = 0; c < 4; c++) {
                int r = c >> 1;
                float p = __expf(sacc[nt][c] - m[r]);
                sacc[nt][c] = p;
                rs[r] += p;
            }
        }
        #pragma unroll
        for (int r = 0; r < 2; r++) {
            rs[r] += __shfl_xor_sync(0xffffffffu, rs[r], 1);
            rs[r] += __shfl_xor_sync(0xffffffffu, rs[r], 2);
            l[r] = l[r] * alpha[r] + rs[r];
        }
        #pragma unroll
        for (int nt = 0; nt < 8; nt++) {
            o[nt][0] *= alpha[0]; o[nt][1] *= alpha[0];
            o[nt][2] *= alpha[1]; o[nt][3] *= alpha[1];
        }

        // ---- store P^T [k][q] (warp-private columns) ----
        #pragma unroll
        for (int nt = 0; nt < 8; nt++)
            #pragma unroll
            for (int c = 0; c < 4; c++) {
                int kpos = nt * 8 + 2 * tg + (c & 1);
                int qrow = w * 16 + g + 8 * (c >> 1);
                Ps[kpos * AST_ + qrow] = f2tf32(sacc[nt][c]);
            }

        // ---- V resident now (hidden behind S + softmax) ----
        if (kt + 1 <= qt) { CP_WAIT(1); } else { CP_WAIT(0); }
        __syncthreads();

        // ---- O += P V (V bits pre-rounded, no cvt) ----
        const uint32_t* VtU = (const uint32_t*)Vraw;
        #pragma unroll
        for (int ks = 0; ks < 8; ks++) {
            const int pbase = (ks * 8 + tg) * AST_ + w * 16 + g;
            uint32_t pa[4];
            pa[0] = Ps[pbase];
            pa[1] = Ps[pbase + 8];
            pa[2] = Ps[pbase + 4 * AST_];
            pa[3] = Ps[pbase + 4 * AST_ + 8];
            #pragma unroll
            for (int nt = 0; nt < 8; nt++) {
                const int vbase = (ks * 8 + tg) * AST_ + nt * 8 + g;
                uint32_t vb[2];
                vb[0] = VtU[vbase];
                vb[1] = VtU[vbase + 4 * AST_];
                mma_tf32(o[nt], pa, vb);
            }
        }
        __syncthreads();
    }
    #undef ISSUE_K
    #undef ISSUE_V

    // ---- finalize & store (tf32-rounded: out_gemm feeds raw bits to mma) ----
    float inv[2] = { 1.0f / l[0], 1.0f / l[1] };
    float* Ob = g_Att + ((size_t)b * S_ + qt * 64) * D_ + h * 64;
    #pragma unroll
    for (int nt = 0; nt < 8; nt++)
        #pragma unroll
        for (int r = 0; r < 2; r++) {
            int row = w * 16 + g + 8 * r;
            int col = nt * 8 + 2 * tg;
            float2 ov;
            ov.x = __uint_as_float(f2tf32(o[nt][2 * r]     * inv[r]));
            ov.y = __uint_as_float(f2tf32(o[nt][2 * r + 1] * inv[r]));
            *(float2*)(Ob + (size_t)row * D_ + col) = ov;
        }
}

// ---------------------------------------------------------------------------
extern "C" void kernel_launch(void* const* d_in, const int* in_sizes, int n_in,
                              void* d_out, int out_size)
{
    (void)in_sizes; (void)n_in; (void)out_size;
    const float* q  = (const float*)d_in[0];
    const float* k  = (const float*)d_in[1];
    const float* v  = (const float*)d_in[2];
    const float* Wq = (const float*)d_in[4];
    const float* bq = (const float*)d_in[5];
    const float* Wk = (const float*)d_in[6];
    const float* bk = (const float*)d_in[7];
    const float* Wv = (const float*)d_in[8];
    const float* bv = (const float*)d_in[9];
    const float* Wo = (const float*)d_in[10];
    const float* bo = (const float*)d_in[11];
    float* out = (float*)d_out;

    const int gemm_smem = 4 * GSTAGE_ * 4;           // 73728 B (2 stages)
    cudaFuncSetAttribute(qkv_gemm_mma, cudaFuncAttributeMaxDynamicSharedMemorySize, gemm_smem);
    cudaFuncSetAttribute(out_gemm_mma, cudaFuncAttributeMaxDynamicSharedMemorySize, gemm_smem);
    const int attn_smem = 4 * 64 * AST_ * 4;         // 69632 B -> 3 CTA/SM
    cudaFuncSetAttribute(attn_kernel, cudaFuncAttributeMaxDynamicSharedMemorySize, attn_smem);

    // pre-round operands to tf32 (bit-identical to cvt-at-fragment-load)
    round_inputs_kernel<<<dim3((B_*S_*D_/4)/256, 3), 256>>>(q, k, v);
    round_weights_kernel<<<dim3((D_*D_/4)/256, 4), 256>>>(Wq, Wk, Wv, Wo);

    dim3 gqkv(1024/128, M_/128, 3);
    qkv_gemm_mma<<<gqkv, 256, gemm_smem>>>(bq, bk, bv);

    attn_kernel<<<dim3(S_/64, H_, B_), 128, attn_smem>>>();

    out_gemm_mma<<<dim3(1024/128, M_/128), 256, gemm_smem>>>(bo, out);
}

// round 16
// speedup vs baseline: 1.0288x; 1.0288x over previous
#include <cuda_runtime.h>
#include <math.h>
#include <stdint.h>

#define B_ 2
#define S_ 2048
#define D_ 1024
#define H_ 16
#define M_ (B_*S_)

// Scratch (allocation-free rule: __device__ globals)
__device__ float g_Qp[(size_t)B_*S_*D_];
__device__ float g_Kp[(size_t)B_*S_*D_];   // tf32-rounded (attn K)
__device__ float g_Vp[(size_t)B_*S_*D_];   // tf32-rounded (attn V)
__device__ float g_Att[(size_t)B_*S_*D_];  // tf32-rounded + k-PERMUTED (out A)
// tf32-rounded + k-PERMUTED copies of GEMM operands (prepass)
__device__ float g_q32[(size_t)B_*S_*D_];
__device__ float g_k32[(size_t)B_*S_*D_];
__device__ float g_v32[(size_t)B_*S_*D_];
__device__ float g_Wq32[(size_t)D_*D_];
__device__ float g_Wk32[(size_t)D_*D_];
__device__ float g_Wv32[(size_t)D_*D_];
__device__ float g_Wo32[(size_t)D_*D_];

__device__ __forceinline__ uint32_t f2tf32(float x) {
    uint32_t r;
    asm("cvt.rna.tf32.f32 %0, %1;" : "=r"(r) : "f"(x));
    return r;
}

__device__ __forceinline__ void mma_tf32(float* d, const uint32_t* a, const uint32_t* b) {
    asm volatile(
        "mma.sync.aligned.m16n8k8.row.col.f32.tf32.tf32.f32 "
        "{%0,%1,%2,%3}, {%4,%5,%6,%7}, {%8,%9}, {%0,%1,%2,%3};"
        : "+f"(d[0]), "+f"(d[1]), "+f"(d[2]), "+f"(d[3])
        : "r"(a[0]), "r"(a[1]), "r"(a[2]), "r"(a[3]), "r"(b[0]), "r"(b[1]));
}

__device__ __forceinline__ uint32_t smem_u32(const void* p) {
    uint32_t a;
    asm("{ .reg .u64 t; cvta.to.shared.u64 t, %1; cvt.u32.u64 %0, t; }"
        : "=r"(a) : "l"(p));
    return a;
}

__device__ __forceinline__ void cp_async16(uint32_t saddr, const void* g) {
    asm volatile("cp.async.cg.shared.global [%0], [%1], 16;"
                 :: "r"(saddr), "l"(g) : "memory");
}
#define CP_COMMIT()  asm volatile("cp.async.commit_group;" ::: "memory")
#define CP_WAIT(n_)  asm volatile("cp.async.wait_group %0;" :: "n"(n_) : "memory")

// ---------------------------------------------------------------------------
// Prepass: tf32-round AND k-permute within each 8-col group.
// Permutation: positions [0..7] hold original cols [0,4,1,5,2,6,3,7]
// => fragment pairs (k, k+4) become adjacent -> LDS.64 at consumer.
// Bit-identical arithmetic (same values, same dot-product pairing).
// Each thread handles one 8-col group (2 float4 in, 2 float4 out).
// ---------------------------------------------------------------------------
__device__ __forceinline__ void round_perm8(const float4* s, uint4* d, size_t gi) {
    float4 a = s[gi * 2], b = s[gi * 2 + 1];
    uint4 lo = { f2tf32(a.x), f2tf32(b.x), f2tf32(a.y), f2tf32(b.y) };
    uint4 hi = { f2tf32(a.z), f2tf32(b.z), f2tf32(a.w), f2tf32(b.w) };
    d[gi * 2] = lo; d[gi * 2 + 1] = hi;
}

__global__ __launch_bounds__(256) void round_inputs_kernel(
    const float* __restrict__ q, const float* __restrict__ k,
    const float* __restrict__ v)
{
    const float* src = (blockIdx.y == 0) ? q : (blockIdx.y == 1) ? k : v;
    float* dst = (blockIdx.y == 0) ? g_q32 : (blockIdx.y == 1) ? g_k32 : g_v32;
    size_t gi = (size_t)blockIdx.x * 256 + threadIdx.x;   // 8-col group index
    round_perm8((const float4*)src, (uint4*)dst, gi);
}

__global__ __launch_bounds__(256) void round_weights_kernel(
    const float* __restrict__ Wq, const float* __restrict__ Wk,
    const float* __restrict__ Wv, const float* __restrict__ Wo)
{
    const float* src = (blockIdx.y == 0) ? Wq : (blockIdx.y == 1) ? Wk :
                       (blockIdx.y == 2) ? Wv : Wo;
    float* dst = (blockIdx.y == 0) ? g_Wq32 : (blockIdx.y == 1) ? g_Wk32 :
                 (blockIdx.y == 2) ? g_Wv32 : g_Wo32;
    size_t gi = (size_t)blockIdx.x * 256 + threadIdx.x;
    round_perm8((const float4*)src, (uint4*)dst, gi);
}

// ---------------------------------------------------------------------------
// tf32 mma.sync GEMM: operands pre-rounded + k-permuted -> fragment loads are
// conflict-free LDS.64, zero cvt. Stride 40 (mod 32 = 8): half-warp banks
// 8g+2tg cover all 32 banks once. Slots/warp-stage: 64 mma + 48 LDS.64.
// ---------------------------------------------------------------------------
#define GST_ 40
#define GSTAGE_ (128*GST_)

template<int DO_ROPE, int ROUND_TF32>
__device__ __forceinline__ void gemm_mma_body(const float* __restrict__ A,
                                              const float* __restrict__ W,
                                              const float* __restrict__ bias,
                                              float* __restrict__ C)
{
    extern __shared__ float gsm_[];
    float* Asf = gsm_;                    // [2][128][40]
    float* Bsf = gsm_ + 2 * GSTAGE_;      // [2][128][40]

    const int tid  = threadIdx.x;
    const int lane = tid & 31, w = tid >> 5;
    const int warpM = w & 1, warpN = w >> 1;
    const int g = lane >> 2, tg = lane & 3;
    const int m0 = blockIdx.y * 128, n0 = blockIdx.x * 128;

    const uint32_t sA_u = smem_u32(Asf);
    const uint32_t sB_u = smem_u32(Bsf);

    #define ISSUE_STAGE(s_, buf_) do {                                        \
        const int k0_ = (s_) * 32;                                            \
        _Pragma("unroll")                                                     \
        for (int t = 0; t < 4; t++) {                                         \
            int slot = tid + t * 256;                                         \
            int r = slot >> 3, qd = slot & 7;                                 \
            uint32_t so = (uint32_t)(((buf_) * GSTAGE_ + r * GST_ + qd * 4) * 4); \
            cp_async16(sA_u + so, A + (size_t)(m0 + r) * 1024 + k0_ + qd * 4);\
            cp_async16(sB_u + so, W + (size_t)(n0 + r) * 1024 + k0_ + qd * 4);\
        }                                                                     \
    } while (0)

    float acc[4][4][4];
    #pragma unroll
    for (int i = 0; i < 4; i++)
        #pragma unroll
        for (int j = 0; j < 4; j++)
            #pragma unroll
            for (int x = 0; x < 4; x++) acc[i][j][x] = 0.f;

    ISSUE_STAGE(0, 0);
    CP_COMMIT();

    #pragma unroll 1
    for (int s = 0; s < 32; s++) {
        if (s + 1 < 32) {
            ISSUE_STAGE(s + 1, (s + 1) & 1);
            CP_COMMIT();
            CP_WAIT(1);
        } else {
            CP_WAIT(0);
        }
        __syncthreads();

        const uint32_t* Ab = (const uint32_t*)(Asf + (s & 1) * GSTAGE_);
        const uint32_t* Bb = (const uint32_t*)(Bsf + (s & 1) * GSTAGE_);
        #pragma unroll
        for (int ks = 0; ks < 4; ks++) {
            const int kc2 = ks * 8 + 2 * tg;     // permuted pair position
            uint32_t af[4][4];
            #pragma unroll
            for (int mt = 0; mt < 4; mt++) {
                const uint32_t* p = Ab + (warpM * 64 + mt * 16 + g) * GST_ + kc2;
                uint2 lo = *(const uint2*)p;                 // (k=tg, k=tg+4)
                uint2 hi = *(const uint2*)(p + 8 * GST_);    // row+8
                af[mt][0] = lo.x; af[mt][1] = hi.x;
                af[mt][2] = lo.y; af[mt][3] = hi.y;
            }
            uint32_t bf[4][2];
            #pragma unroll
            for (int nt = 0; nt < 4; nt++) {
                uint2 bb = *(const uint2*)(Bb + (warpN * 8 + nt * 32 + g) * GST_ + kc2);
                bf[nt][0] = bb.x; bf[nt][1] = bb.y;
            }
            #pragma unroll
            for (int mt = 0; mt < 4; mt++)
                #pragma unroll
                for (int nt = 0; nt < 4; nt++)
                    mma_tf32(acc[mt][nt], af[mt], bf[nt]);
        }
        __syncthreads();
    }
    #undef ISSUE_STAGE

    float bcol[4][2];
    #pragma unroll
    for (int nt = 0; nt < 4; nt++) {
        bcol[nt][0] = bias[n0 + warpN * 8 + nt * 32 + 2 * tg + 0];
        bcol[nt][1] = bias[n0 + warpN * 8 + nt * 32 + 2 * tg + 1];
    }
    #pragma unroll
    for (int mt = 0; mt < 4; mt++)
        #pragma unroll
        for (int nt = 0; nt < 4; nt++) {
            acc[mt][nt][0] += bcol[nt][0];
            acc[mt][nt][1] += bcol[nt][1];
            acc[mt][nt][2] += bcol[nt][0];
            acc[mt][nt][3] += bcol[nt][1];
        }

    if (DO_ROPE) {
        float sn[2][8], cs[2][8];
        #pragma unroll
        for (int jj = 0; jj < 2; jj++) {
            int jcol = warpN * 8 + 2 * tg + jj;
            float invf = (float)exp(-(double)jcol * 0.28782313662425574);
            #pragma unroll
            for (int mt = 0; mt < 4; mt++)
                #pragma unroll
                for (int half = 0; half < 2; half++) {
                    int row = m0 + warpM * 64 + mt * 16 + g + 8 * half;
                    float sp = (float)(row & (S_ - 1));
                    sincosf(sp * invf, &sn[jj][mt * 2 + half], &cs[jj][mt * 2 + half]);
                }
        }
        #pragma unroll
        for (int mt = 0; mt < 4; mt++)
            #pragma unroll
            for (int p = 0; p < 2; p++)
                #pragma unroll
                for (int idx = 0; idx < 4; idx++) {
                    int jj = idx & 1, half = idx >> 1;
                    float c = cs[jj][mt * 2 + half], s = sn[jj][mt * 2 + half];
                    float x1 = acc[mt][2 * p][idx], x2 = acc[mt][2 * p + 1][idx];
                    acc[mt][2 * p][idx]     = x1 * c - x2 * s;
                    acc[mt][2 * p + 1][idx] = x1 * s + x2 * c;
                }
    }

    #pragma unroll
    for (int mt = 0; mt < 4; mt++)
        #pragma unroll
        for (int nt = 0; nt < 4; nt++)
            #pragma unroll
            for (int half = 0; half < 2; half++) {
                int row = m0 + warpM * 64 + mt * 16 + g + 8 * half;
                int col = n0 + warpN * 8 + nt * 32 + 2 * tg;
                float2 ov;
                if (ROUND_TF32) {
                    ov.x = __uint_as_float(f2tf32(acc[mt][nt][half * 2]));
                    ov.y = __uint_as_float(f2tf32(acc[mt][nt][half * 2 + 1]));
                } else {
                    ov.x = acc[mt][nt][half * 2];
                    ov.y = acc[mt][nt][half * 2 + 1];
                }
                *(float2*)(C + (size_t)row * 1024 + col) = ov;
            }
}

__global__ __launch_bounds__(256, 2)
void qkv_gemm_mma(const float* __restrict__ bq, const float* __restrict__ bk,
                  const float* __restrict__ bv)
{
    if (blockIdx.z == 0)      gemm_mma_body<1, 0>(g_q32, g_Wq32, bq, g_Qp);
    else if (blockIdx.z == 1) gemm_mma_body<1, 1>(g_k32, g_Wk32, bk, g_Kp);
    else                      gemm_mma_body<0, 1>(g_v32, g_Wv32, bv, g_Vp);
}

__global__ __launch_bounds__(256, 2)
void out_gemm_mma(const float* __restrict__ bo, float* __restrict__ out)
{
    gemm_mma_body<0, 0>(g_Att, g_Wo32, bo, out);
}

// ---------------------------------------------------------------------------
// Causal flash attention (round-12 best-measured config; body unchanged).
// Epilogue stores g_Att tf32-rounded AND k-permuted (for out_gemm LDS.64).
// smem = 4*64*68*4 = 69632 B -> 3 CTAs/SM.
// ---------------------------------------------------------------------------
#define AST_ 68
__global__ __launch_bounds__(128, 3) void attn_kernel()
{
    extern __shared__ float afm_[];
    float*    Kraw = afm_;                          // [2][64][68] (tf32 bits)
    float*    Vraw = afm_ + 2 * 64 * AST_;          // [64][68]    (tf32 bits)
    uint32_t* Ps   = (uint32_t*)(afm_ + 3 * 64 * AST_);

    const int tid = threadIdx.x;
    const int lane = tid & 31, w = tid >> 5;
    const int g = lane >> 2, tg = lane & 3;
    const int qt = (int)(gridDim.x - 1) - (int)blockIdx.x;   // heavy first
    const int h = blockIdx.y, b = blockIdx.z;

    const float* Qb = g_Qp + ((size_t)b * S_ + qt * 64) * D_ + h * 64;
    const float* Kb = g_Kp + (size_t)b * S_ * D_ + h * 64;
    const float* Vb = g_Vp + (size_t)b * S_ * D_ + h * 64;

    const uint32_t kraw_u = smem_u32(Kraw);
    const uint32_t vraw_u = smem_u32(Vraw);

    #define ISSUE_K(kt_, buf_) do {                                           \
        _Pragma("unroll")                                                     \
        for (int t = 0; t < 8; t++) {                                         \
            int slot = tid + t * 128;                                         \
            int r = slot >> 4, qd = slot & 15;                                \
            uint32_t so = (uint32_t)((((buf_) * 64 + r) * AST_ + qd * 4) * 4);\
            cp_async16(kraw_u + so, Kb + (size_t)((kt_) * 64 + r) * D_ + qd * 4); \
        }                                                                     \
    } while (0)
    #define ISSUE_V(kt_) do {                                                 \
        _Pragma("unroll")                                                     \
        for (int t = 0; t < 8; t++) {                                         \
            int slot = tid + t * 128;                                         \
            int r = slot >> 4, qd = slot & 15;                                \
            uint32_t so = (uint32_t)((r * AST_ + qd * 4) * 4);                \
            cp_async16(vraw_u + so, Vb + (size_t)((kt_) * 64 + r) * D_ + qd * 4); \
        }                                                                     \
    } while (0)

    ISSUE_K(0, 0); CP_COMMIT();

    // ---- Q a-fragments into registers (scaled 1/8, tf32, kt-invariant) ----
    uint32_t qf[8][4];
    {
        const float* q0 = Qb + (size_t)(w * 16 + g) * D_;
        const float* q1 = Qb + (size_t)(w * 16 + g + 8) * D_;
        #pragma unroll
        for (int ks = 0; ks < 8; ks++) {
            int c = ks * 8 + tg;
            qf[ks][0] = f2tf32(q0[c]     * 0.125f);
            qf[ks][1] = f2tf32(q1[c]     * 0.125f);
            qf[ks][2] = f2tf32(q0[c + 4] * 0.125f);
            qf[ks][3] = f2tf32(q1[c + 4] * 0.125f);
        }
    }

    float m[2], l[2], o[8][4];
    m[0] = m[1] = -INFINITY; l[0] = l[1] = 0.f;
    #pragma unroll
    for (int nt = 0; nt < 8; nt++)
        #pragma unroll
        for (int c = 0; c < 4; c++) o[nt][c] = 0.f;

    #pragma unroll 1
    for (int kt = 0; kt <= qt; kt++) {
        ISSUE_V(kt); CP_COMMIT();
        if (kt + 1 <= qt) {
            ISSUE_K(kt + 1, (kt + 1) & 1); CP_COMMIT();
            CP_WAIT(2);
        } else {
            CP_WAIT(1);
        }
        __syncthreads();

        const uint32_t* KtU = (const uint32_t*)(Kraw + (kt & 1) * 64 * AST_);

        // ---- S = Q K^T (1xTF32; K bits pre-rounded) ----
        float sacc[8][4];
        #pragma unroll
        for (int nt = 0; nt < 8; nt++)
            #pragma unroll
            for (int c = 0; c < 4; c++) sacc[nt][c] = 0.f;

        #pragma unroll
        for (int ks = 0; ks < 8; ks++) {
            #pragma unroll
            for (int nt = 0; nt < 8; nt++) {
                const int bbase = (nt * 8 + g) * AST_ + ks * 8 + tg;
                uint32_t bh[2];
                bh[0] = KtU[bbase];
                bh[1] = KtU[bbase + 4];
                mma_tf32(sacc[nt], qf[ks], bh);
            }
        }

        // ---- masking (diag tile only) ----
        if (kt == qt) {
            #pragma unroll
            for (int nt = 0; nt < 8; nt++)
                #pragma unroll
                for (int c = 0; c < 4; c++) {
                    int colL = nt * 8 + 2 * tg + (c & 1);
                    int rowL = w * 16 + g + 8 * (c >> 1);
                    if (colL > rowL) sacc[nt][c] = -INFINITY;
                }
        }

        // ---- online softmax ----
        float rm[2] = {-INFINITY, -INFINITY};
        #pragma unroll
        for (int nt = 0; nt < 8; nt++) {
            rm[0] = fmaxf(rm[0], fmaxf(sacc[nt][0], sacc[nt][1]));
            rm[1] = fmaxf(rm[1], fmaxf(sacc[nt][2], sacc[nt][3]));
        }
        #pragma unroll
        for (int r = 0; r < 2; r++) {
            rm[r] = fmaxf(rm[r], __shfl_xor_sync(0xffffffffu, rm[r], 1));
            rm[r] = fmaxf(rm[r], __shfl_xor_sync(0xffffffffu, rm[r], 2));
        }
        float alpha[2], rs[2];
        #pragma unroll
        for (int r = 0; r < 2; r++) {
            float mn = fmaxf(m[r], rm[r]);
            alpha[r] = __expf(m[r] - mn);
            m[r] = mn;
            rs[r] = 0.f;
        }
        #pragma unroll
        for (int nt = 0; nt < 8; nt++) {
            #pragma unroll
            for (int c = 0; c < 4; c++) {
                int r = c >> 1;
                float p = __expf(sacc[nt][c] - m[r]);
                sacc[nt][c] = p;
                rs[r] += p;
            }
        }
        #pragma unroll
        for (int r = 0; r < 2; r++) {
            rs[r] += __shfl_xor_sync(0xffffffffu, rs[r], 1);
            rs[r] += __shfl_xor_sync(0xffffffffu, rs[r], 2);
            l[r] = l[r] * alpha[r] + rs[r];
        }
        #pragma unroll
        for (int nt = 0; nt < 8; nt++) {
            o[nt][0] *= alpha[0]; o[nt][1] *= alpha[0];
            o[nt][2] *= alpha[1]; o[nt][3] *= alpha[1];
        }

        // ---- store P^T [k][q] (warp-private columns) ----
        #pragma unroll
        for (int nt = 0; nt < 8; nt++)
            #pragma unroll
            for (int c = 0; c < 4; c++) {
                int kpos = nt * 8 + 2 * tg + (c & 1);
                int qrow = w * 16 + g + 8 * (c >> 1);
                Ps[kpos * AST_ + qrow] = f2tf32(sacc[nt][c]);
            }

        // ---- V resident now ----
        if (kt + 1 <= qt) { CP_WAIT(1); } else { CP_WAIT(0); }
        __syncthreads();

        // ---- O += P V (V bits pre-rounded) ----
        const uint32_t* VtU = (const uint32_t*)Vraw;
        #pragma unroll
        for (int ks = 0; ks < 8; ks++) {
            const int pbase = (ks * 8 + tg) * AST_ + w * 16 + g;
            uint32_t pa[4];
            pa[0] = Ps[pbase];
            pa[1] = Ps[pbase + 8];
            pa[2] = Ps[pbase + 4 * AST_];
            pa[3] = Ps[pbase + 4 * AST_ + 8];
            #pragma unroll
            for (int nt = 0; nt < 8; nt++) {
                const int vbase = (ks * 8 + tg) * AST_ + nt * 8 + g;
                uint32_t vb[2];
                vb[0] = VtU[vbase];
                vb[1] = VtU[vbase + 4 * AST_];
                mma_tf32(o[nt], pa, vb);
            }
        }
        __syncthreads();
    }
    #undef ISSUE_K
    #undef ISSUE_V

    // ---- finalize & store: tf32-rounded + k-PERMUTED for out_gemm ----
    // within each 8-col group: orig col j -> position (j<4 ? 2j : 2j-7)
    float inv[2] = { 1.0f / l[0], 1.0f / l[1] };
    float* Ob = g_Att + ((size_t)b * S_ + qt * 64) * D_ + h * 64;
    const int j0 = 2 * tg, j1 = 2 * tg + 1;
    const int p0 = (j0 < 4) ? 2 * j0 : 2 * j0 - 7;
    const int p1 = (j1 < 4) ? 2 * j1 : 2 * j1 - 7;
    #pragma unroll
    for (int nt = 0; nt < 8; nt++)
        #pragma unroll
        for (int r = 0; r < 2; r++) {
            int row = w * 16 + g + 8 * r;
            float* rp = Ob + (size_t)row * D_ + nt * 8;
            rp[p0] = __uint_as_float(f2tf32(o[nt][2 * r]     * inv[r]));
            rp[p1] = __uint_as_float(f2tf32(o[nt][2 * r + 1] * inv[r]));
        }
}

// ---------------------------------------------------------------------------
extern "C" void kernel_launch(void* const* d_in, const int* in_sizes, int n_in,
                              void* d_out, int out_size)
{
    (void)in_sizes; (void)n_in; (void)out_size;
    const float* q  = (const float*)d_in[0];
    const float* k  = (const float*)d_in[1];
    const float* v  = (const float*)d_in[2];
    const float* Wq = (const float*)d_in[4];
    const float* bq = (const float*)d_in[5];
    const float* Wk = (const float*)d_in[6];
    const float* bk = (const float*)d_in[7];
    const float* Wv = (const float*)d_in[8];
    const float* bv = (const float*)d_in[9];
    const float* Wo = (const float*)d_in[10];
    const float* bo = (const float*)d_in[11];
    float* out = (float*)d_out;

    const int gemm_smem = 4 * GSTAGE_ * 4;           // 81920 B (2 stages)
    cudaFuncSetAttribute(qkv_gemm_mma, cudaFuncAttributeMaxDynamicSharedMemorySize, gemm_smem);
    cudaFuncSetAttribute(out_gemm_mma, cudaFuncAttributeMaxDynamicSharedMemorySize, gemm_smem);
    const int attn_smem = 4 * 64 * AST_ * 4;         // 69632 B -> 3 CTA/SM
    cudaFuncSetAttribute(attn_kernel, cudaFuncAttributeMaxDynamicSharedMemorySize, attn_smem);

    // prepass: tf32-round + k-permute (bit-identical numerics)
    round_inputs_kernel<<<dim3((B_*S_*D_/8)/256, 3), 256>>>(q, k, v);
    round_weights_kernel<<<dim3((D_*D_/8)/256, 4), 256>>>(Wq, Wk, Wv, Wo);

    dim3 gqkv(1024/128, M_/128, 3);
    qkv_gemm_mma<<<gqkv, 256, gemm_smem>>>(bq, bk, bv);

    attn_kernel<<<dim3(S_/64, H_, B_), 128, attn_smem>>>();

    out_gemm_mma<<<dim3(1024/128, M_/128), 256, gemm_smem>>>(bo, out);
}

// round 17
// speedup vs baseline: 1.0567x; 1.0272x over previous
#include <cuda_runtime.h>
#include <math.h>
#include <stdint.h>

#define B_ 2
#define S_ 2048
#define D_ 1024
#define H_ 16
#define M_ (B_*S_)

// Scratch (allocation-free rule: __device__ globals)
__device__ float g_Qp[(size_t)B_*S_*D_];   // d-PERMUTED (attn Q)
__device__ float g_Kp[(size_t)B_*S_*D_];   // tf32-rounded + d-PERMUTED (attn K)
__device__ float g_Vp[(size_t)B_*S_*D_];   // tf32-rounded (attn V, unpermuted)
__device__ float g_Att[(size_t)B_*S_*D_];  // tf32-rounded + k-PERMUTED (out A)
// tf32-rounded + k-PERMUTED copies of GEMM operands (prepass)
__device__ float g_q32[(size_t)B_*S_*D_];
__device__ float g_k32[(size_t)B_*S_*D_];
__device__ float g_v32[(size_t)B_*S_*D_];
__device__ float g_Wq32[(size_t)D_*D_];
__device__ float g_Wk32[(size_t)D_*D_];
__device__ float g_Wv32[(size_t)D_*D_];
__device__ float g_Wo32[(size_t)D_*D_];

__device__ __forceinline__ uint32_t f2tf32(float x) {
    uint32_t r;
    asm("cvt.rna.tf32.f32 %0, %1;" : "=r"(r) : "f"(x));
    return r;
}

__device__ __forceinline__ void mma_tf32(float* d, const uint32_t* a, const uint32_t* b) {
    asm volatile(
        "mma.sync.aligned.m16n8k8.row.col.f32.tf32.tf32.f32 "
        "{%0,%1,%2,%3}, {%4,%5,%6,%7}, {%8,%9}, {%0,%1,%2,%3};"
        : "+f"(d[0]), "+f"(d[1]), "+f"(d[2]), "+f"(d[3])
        : "r"(a[0]), "r"(a[1]), "r"(a[2]), "r"(a[3]), "r"(b[0]), "r"(b[1]));
}

__device__ __forceinline__ uint32_t smem_u32(const void* p) {
    uint32_t a;
    asm("{ .reg .u64 t; cvta.to.shared.u64 t, %1; cvt.u32.u64 %0, t; }"
        : "=r"(a) : "l"(p));
    return a;
}

__device__ __forceinline__ void cp_async16(uint32_t saddr, const void* g) {
    asm volatile("cp.async.cg.shared.global [%0], [%1], 16;"
                 :: "r"(saddr), "l"(g) : "memory");
}
#define CP_COMMIT()  asm volatile("cp.async.commit_group;" ::: "memory")
#define CP_WAIT(n_)  asm volatile("cp.async.wait_group %0;" :: "n"(n_) : "memory")

// ---------------------------------------------------------------------------
// Prepass: tf32-round + k-permute [0,4,1,5,2,6,3,7] within 8-col groups.
// ---------------------------------------------------------------------------
__device__ __forceinline__ void round_perm8(const float4* s, uint4* d, size_t gi) {
    float4 a = s[gi * 2], b = s[gi * 2 + 1];
    uint4 lo = { f2tf32(a.x), f2tf32(b.x), f2tf32(a.y), f2tf32(b.y) };
    uint4 hi = { f2tf32(a.z), f2tf32(b.z), f2tf32(a.w), f2tf32(b.w) };
    d[gi * 2] = lo; d[gi * 2 + 1] = hi;
}

__global__ __launch_bounds__(256) void round_inputs_kernel(
    const float* __restrict__ q, const float* __restrict__ k,
    const float* __restrict__ v)
{
    const float* src = (blockIdx.y == 0) ? q : (blockIdx.y == 1) ? k : v;
    float* dst = (blockIdx.y == 0) ? g_q32 : (blockIdx.y == 1) ? g_k32 : g_v32;
    size_t gi = (size_t)blockIdx.x * 256 + threadIdx.x;
    round_perm8((const float4*)src, (uint4*)dst, gi);
}

__global__ __launch_bounds__(256) void round_weights_kernel(
    const float* __restrict__ Wq, const float* __restrict__ Wk,
    const float* __restrict__ Wv, const float* __restrict__ Wo)
{
    const float* src = (blockIdx.y == 0) ? Wq : (blockIdx.y == 1) ? Wk :
                       (blockIdx.y == 2) ? Wv : Wo;
    float* dst = (blockIdx.y == 0) ? g_Wq32 : (blockIdx.y == 1) ? g_Wk32 :
                 (blockIdx.y == 2) ? g_Wv32 : g_Wo32;
    size_t gi = (size_t)blockIdx.x * 256 + threadIdx.x;
    round_perm8((const float4*)src, (uint4*)dst, gi);
}

// ---------------------------------------------------------------------------
// tf32 mma.sync GEMM: pre-rounded + k-permuted operands -> LDS.64 fragments,
// zero cvt. PERM_OUT: store output columns k-permuted (for downstream LDS.64
// consumers). Store-position change only; values bit-identical.
// ---------------------------------------------------------------------------
#define GST_ 40
#define GSTAGE_ (128*GST_)

template<int DO_ROPE, int ROUND_TF32, int PERM_OUT>
__device__ __forceinline__ void gemm_mma_body(const float* __restrict__ A,
                                              const float* __restrict__ W,
                                              const float* __restrict__ bias,
                                              float* __restrict__ C)
{
    extern __shared__ float gsm_[];
    float* Asf = gsm_;                    // [2][128][40]
    float* Bsf = gsm_ + 2 * GSTAGE_;      // [2][128][40]

    const int tid  = threadIdx.x;
    const int lane = tid & 31, w = tid >> 5;
    const int warpM = w & 1, warpN = w >> 1;
    const int g = lane >> 2, tg = lane & 3;
    const int m0 = blockIdx.y * 128, n0 = blockIdx.x * 128;

    const uint32_t sA_u = smem_u32(Asf);
    const uint32_t sB_u = smem_u32(Bsf);

    #define ISSUE_STAGE(s_, buf_) do {                                        \
        const int k0_ = (s_) * 32;                                            \
        _Pragma("unroll")                                                     \
        for (int t = 0; t < 4; t++) {                                         \
            int slot = tid + t * 256;                                         \
            int r = slot >> 3, qd = slot & 7;                                 \
            uint32_t so = (uint32_t)(((buf_) * GSTAGE_ + r * GST_ + qd * 4) * 4); \
            cp_async16(sA_u + so, A + (size_t)(m0 + r) * 1024 + k0_ + qd * 4);\
            cp_async16(sB_u + so, W + (size_t)(n0 + r) * 1024 + k0_ + qd * 4);\
        }                                                                     \
    } while (0)

    float acc[4][4][4];
    #pragma unroll
    for (int i = 0; i < 4; i++)
        #pragma unroll
        for (int j = 0; j < 4; j++)
            #pragma unroll
            for (int x = 0; x < 4; x++) acc[i][j][x] = 0.f;

    ISSUE_STAGE(0, 0);
    CP_COMMIT();

    #pragma unroll 1
    for (int s = 0; s < 32; s++) {
        if (s + 1 < 32) {
            ISSUE_STAGE(s + 1, (s + 1) & 1);
            CP_COMMIT();
            CP_WAIT(1);
        } else {
            CP_WAIT(0);
        }
        __syncthreads();

        const uint32_t* Ab = (const uint32_t*)(Asf + (s & 1) * GSTAGE_);
        const uint32_t* Bb = (const uint32_t*)(Bsf + (s & 1) * GSTAGE_);
        #pragma unroll
        for (int ks = 0; ks < 4; ks++) {
            const int kc2 = ks * 8 + 2 * tg;
            uint32_t af[4][4];
            #pragma unroll
            for (int mt = 0; mt < 4; mt++) {
                const uint32_t* p = Ab + (warpM * 64 + mt * 16 + g) * GST_ + kc2;
                uint2 lo = *(const uint2*)p;
                uint2 hi = *(const uint2*)(p + 8 * GST_);
                af[mt][0] = lo.x; af[mt][1] = hi.x;
                af[mt][2] = lo.y; af[mt][3] = hi.y;
            }
            uint32_t bf[4][2];
            #pragma unroll
            for (int nt = 0; nt < 4; nt++) {
                uint2 bb = *(const uint2*)(Bb + (warpN * 8 + nt * 32 + g) * GST_ + kc2);
                bf[nt][0] = bb.x; bf[nt][1] = bb.y;
            }
            #pragma unroll
            for (int mt = 0; mt < 4; mt++)
                #pragma unroll
                for (int nt = 0; nt < 4; nt++)
                    mma_tf32(acc[mt][nt], af[mt], bf[nt]);
        }
        __syncthreads();
    }
    #undef ISSUE_STAGE

    float bcol[4][2];
    #pragma unroll
    for (int nt = 0; nt < 4; nt++) {
        bcol[nt][0] = bias[n0 + warpN * 8 + nt * 32 + 2 * tg + 0];
        bcol[nt][1] = bias[n0 + warpN * 8 + nt * 32 + 2 * tg + 1];
    }
    #pragma unroll
    for (int mt = 0; mt < 4; mt++)
        #pragma unroll
        for (int nt = 0; nt < 4; nt++) {
            acc[mt][nt][0] += bcol[nt][0];
            acc[mt][nt][1] += bcol[nt][1];
            acc[mt][nt][2] += bcol[nt][0];
            acc[mt][nt][3] += bcol[nt][1];
        }

    if (DO_ROPE) {
        float sn[2][8], cs[2][8];
        #pragma unroll
        for (int jj = 0; jj < 2; jj++) {
            int jcol = warpN * 8 + 2 * tg + jj;
            float invf = (float)exp(-(double)jcol * 0.28782313662425574);
            #pragma unroll
            for (int mt = 0; mt < 4; mt++)
                #pragma unroll
                for (int half = 0; half < 2; half++) {
                    int row = m0 + warpM * 64 + mt * 16 + g + 8 * half;
                    float sp = (float)(row & (S_ - 1));
                    sincosf(sp * invf, &sn[jj][mt * 2 + half], &cs[jj][mt * 2 + half]);
                }
        }
        #pragma unroll
        for (int mt = 0; mt < 4; mt++)
            #pragma unroll
            for (int p = 0; p < 2; p++)
                #pragma unroll
                for (int idx = 0; idx < 4; idx++) {
                    int jj = idx & 1, half = idx >> 1;
                    float c = cs[jj][mt * 2 + half], s = sn[jj][mt * 2 + half];
                    float x1 = acc[mt][2 * p][idx], x2 = acc[mt][2 * p + 1][idx];
                    acc[mt][2 * p][idx]     = x1 * c - x2 * s;
                    acc[mt][2 * p + 1][idx] = x1 * s + x2 * c;
                }
    }

    // store: original col j = (group base) + 2tg + {0,1};
    // PERM_OUT places within-group position (j<4 ? 2j : 2j-7)
    const int j0 = 2 * tg, j1 = 2 * tg + 1;
    const int p0 = (j0 < 4) ? 2 * j0 : 2 * j0 - 7;
    const int p1 = (j1 < 4) ? 2 * j1 : 2 * j1 - 7;
    #pragma unroll
    for (int mt = 0; mt < 4; mt++)
        #pragma unroll
        for (int nt = 0; nt < 4; nt++)
            #pragma unroll
            for (int half = 0; half < 2; half++) {
                int row = m0 + warpM * 64 + mt * 16 + g + 8 * half;
                float vx = acc[mt][nt][half * 2];
                float vy = acc[mt][nt][half * 2 + 1];
                if (ROUND_TF32) {
                    vx = __uint_as_float(f2tf32(vx));
                    vy = __uint_as_float(f2tf32(vy));
                }
                if (PERM_OUT) {
                    float* rp = C + (size_t)row * 1024 + n0 + warpN * 8 + nt * 32;
                    rp[p0] = vx;
                    rp[p1] = vy;
                } else {
                    int col = n0 + warpN * 8 + nt * 32 + 2 * tg;
                    float2 ov = { vx, vy };
                    *(float2*)(C + (size_t)row * 1024 + col) = ov;
                }
            }
}

__global__ __launch_bounds__(256, 2)
void qkv_gemm_mma(const float* __restrict__ bq, const float* __restrict__ bk,
                  const float* __restrict__ bv)
{
    if (blockIdx.z == 0)      gemm_mma_body<1, 0, 1>(g_q32, g_Wq32, bq, g_Qp);
    else if (blockIdx.z == 1) gemm_mma_body<1, 1, 1>(g_k32, g_Wk32, bk, g_Kp);
    else                      gemm_mma_body<0, 1, 0>(g_v32, g_Wv32, bv, g_Vp);
}

__global__ __launch_bounds__(256, 2)
void out_gemm_mma(const float* __restrict__ bo, float* __restrict__ out)
{
    gemm_mma_body<0, 0, 0>(g_Att, g_Wo32, bo, out);
}

// ---------------------------------------------------------------------------
// Causal flash attention: r12 config + d-permuted Q/K -> S-phase K fragments
// are conflict-free LDS.64 (K tile stride 72 = 8 mod 32; half-warp banks
// 8g+2tg distinct). V/Ps keep stride 68 (conflict-free as before).
// smem = (2*64*72 + 2*64*68)*4 = 71680 B -> 3 CTAs/SM.
// ---------------------------------------------------------------------------
#define KST_ 72
#define VST_ 68
__global__ __launch_bounds__(128, 3) void attn_kernel()
{
    extern __shared__ float afm_[];
    float*    Kraw = afm_;                            // [2][64][72] (tf32 bits)
    float*    Vraw = afm_ + 2 * 64 * KST_;            // [64][68]
    uint32_t* Ps   = (uint32_t*)(afm_ + 2 * 64 * KST_ + 64 * VST_);

    const int tid = threadIdx.x;
    const int lane = tid & 31, w = tid >> 5;
    const int g = lane >> 2, tg = lane & 3;
    const int qt = (int)(gridDim.x - 1) - (int)blockIdx.x;   // heavy first
    const int h = blockIdx.y, b = blockIdx.z;

    const float* Qb = g_Qp + ((size_t)b * S_ + qt * 64) * D_ + h * 64;
    const float* Kb = g_Kp + (size_t)b * S_ * D_ + h * 64;
    const float* Vb = g_Vp + (size_t)b * S_ * D_ + h * 64;

    const uint32_t kraw_u = smem_u32(Kraw);
    const uint32_t vraw_u = smem_u32(Vraw);

    #define ISSUE_K(kt_, buf_) do {                                           \
        _Pragma("unroll")                                                     \
        for (int t = 0; t < 8; t++) {                                         \
            int slot = tid + t * 128;                                         \
            int r = slot >> 4, qd = slot & 15;                                \
            uint32_t so = (uint32_t)((((buf_) * 64 + r) * KST_ + qd * 4) * 4);\
            cp_async16(kraw_u + so, Kb + (size_t)((kt_) * 64 + r) * D_ + qd * 4); \
        }                                                                     \
    } while (0)
    #define ISSUE_V(kt_) do {                                                 \
        _Pragma("unroll")                                                     \
        for (int t = 0; t < 8; t++) {                                         \
            int slot = tid + t * 128;                                         \
            int r = slot >> 4, qd = slot & 15;                                \
            uint32_t so = (uint32_t)((r * VST_ + qd * 4) * 4);                \
            cp_async16(vraw_u + so, Vb + (size_t)((kt_) * 64 + r) * D_ + qd * 4); \
        }                                                                     \
    } while (0)

    ISSUE_K(0, 0); CP_COMMIT();

    // ---- Q a-fragments (g_Qp is d-permuted: float2 at ks*8+2tg = (c, c+4)) ----
    uint32_t qf[8][4];
    {
        const float2* q0 = (const float2*)(Qb + (size_t)(w * 16 + g) * D_);
        const float2* q1 = (const float2*)(Qb + (size_t)(w * 16 + g + 8) * D_);
        #pragma unroll
        for (int ks = 0; ks < 8; ks++) {
            float2 a0 = q0[ks * 4 + tg];
            float2 a1 = q1[ks * 4 + tg];
            qf[ks][0] = f2tf32(a0.x * 0.125f);
            qf[ks][1] = f2tf32(a1.x * 0.125f);
            qf[ks][2] = f2tf32(a0.y * 0.125f);
            qf[ks][3] = f2tf32(a1.y * 0.125f);
        }
    }

    float m[2], l[2], o[8][4];
    m[0] = m[1] = -INFINITY; l[0] = l[1] = 0.f;
    #pragma unroll
    for (int nt = 0; nt < 8; nt++)
        #pragma unroll
        for (int c = 0; c < 4; c++) o[nt][c] = 0.f;

    #pragma unroll 1
    for (int kt = 0; kt <= qt; kt++) {
        ISSUE_V(kt); CP_COMMIT();
        if (kt + 1 <= qt) {
            ISSUE_K(kt + 1, (kt + 1) & 1); CP_COMMIT();
            CP_WAIT(2);
        } else {
            CP_WAIT(1);
        }
        __syncthreads();

        const uint2* Kt2 = (const uint2*)(Kraw + (kt & 1) * 64 * KST_);

        // ---- S = Q K^T (1xTF32; K pre-rounded + d-permuted -> LDS.64) ----
        float sacc[8][4];
        #pragma unroll
        for (int nt = 0; nt < 8; nt++)
            #pragma unroll
            for (int c = 0; c < 4; c++) sacc[nt][c] = 0.f;

        #pragma unroll
        for (int ks = 0; ks < 8; ks++) {
            #pragma unroll
            for (int nt = 0; nt < 8; nt++) {
                uint2 bb = Kt2[(nt * 8 + g) * (KST_ / 2) + ks * 4 + tg];
                uint32_t bh[2] = { bb.x, bb.y };
                mma_tf32(sacc[nt], qf[ks], bh);
            }
        }

        // ---- masking (diag tile only) ----
        if (kt == qt) {
            #pragma unroll
            for (int nt = 0; nt < 8; nt++)
                #pragma unroll
                for (int c = 0; c < 4; c++) {
                    int colL = nt * 8 + 2 * tg + (c & 1);
                    int rowL = w * 16 + g + 8 * (c >> 1);
                    if (colL > rowL) sacc[nt][c] = -INFINITY;
                }
        }

        // ---- online softmax ----
        float rm[2] = {-INFINITY, -INFINITY};
        #pragma unroll
        for (int nt = 0; nt < 8; nt++) {
            rm[0] = fmaxf(rm[0], fmaxf(sacc[nt][0], sacc[nt][1]));
            rm[1] = fmaxf(rm[1], fmaxf(sacc[nt][2], sacc[nt][3]));
        }
        #pragma unroll
        for (int r = 0; r < 2; r++) {
            rm[r] = fmaxf(rm[r], __shfl_xor_sync(0xffffffffu, rm[r], 1));
            rm[r] = fmaxf(rm[r], __shfl_xor_sync(0xffffffffu, rm[r], 2));
        }
        float alpha[2], rs[2];
        #pragma unroll
        for (int r = 0; r < 2; r++) {
            float mn = fmaxf(m[r], rm[r]);
            alpha[r] = __expf(m[r] - mn);
            m[r] = mn;
            rs[r] = 0.f;
        }
        #pragma unroll
        for (int nt = 0; nt < 8; nt++) {
            #pragma unroll
            for (int c = 0; c < 4; c++) {
                int r = c >> 1;
                float p = __expf(sacc[nt][c] - m[r]);
                sacc[nt][c] = p;
                rs[r] += p;
            }
        }
        #pragma unroll
        for (int r = 0; r < 2; r++) {
            rs[r] += __shfl_xor_sync(0xffffffffu, rs[r], 1);
            rs[r] += __shfl_xor_sync(0xffffffffu, rs[r], 2);
            l[r] = l[r] * alpha[r] + rs[r];
        }
        #pragma unroll
        for (int nt = 0; nt < 8; nt++) {
            o[nt][0] *= alpha[0]; o[nt][1] *= alpha[0];
            o[nt][2] *= alpha[1]; o[nt][3] *= alpha[1];
        }

        // ---- store P^T [k][q] (warp-private columns) ----
        #pragma unroll
        for (int nt = 0; nt < 8; nt++)
            #pragma unroll
            for (int c = 0; c < 4; c++) {
                int kpos = nt * 8 + 2 * tg + (c & 1);
                int qrow = w * 16 + g + 8 * (c >> 1);
                Ps[kpos * VST_ + qrow] = f2tf32(sacc[nt][c]);
            }

        // ---- V resident now ----
        if (kt + 1 <= qt) { CP_WAIT(1); } else { CP_WAIT(0); }
        __syncthreads();

        // ---- O += P V (V bits pre-rounded) ----
        const uint32_t* VtU = (const uint32_t*)Vraw;
        #pragma unroll
        for (int ks = 0; ks < 8; ks++) {
            const int pbase = (ks * 8 + tg) * VST_ + w * 16 + g;
            uint32_t pa[4];
            pa[0] = Ps[pbase];
            pa[1] = Ps[pbase + 8];
            pa[2] = Ps[pbase + 4 * VST_];
            pa[3] = Ps[pbase + 4 * VST_ + 8];
            #pragma unroll
            for (int nt = 0; nt < 8; nt++) {
                const int vbase = (ks * 8 + tg) * VST_ + nt * 8 + g;
                uint32_t vb[2];
                vb[0] = VtU[vbase];
                vb[1] = VtU[vbase + 4 * VST_];
                mma_tf32(o[nt], pa, vb);
            }
        }
        __syncthreads();
    }
    #undef ISSUE_K
    #undef ISSUE_V

    // ---- finalize & store: tf32-rounded + k-PERMUTED for out_gemm ----
    float inv[2] = { 1.0f / l[0], 1.0f / l[1] };
    float* Ob = g_Att + ((size_t)b * S_ + qt * 64) * D_ + h * 64;
    const int j0 = 2 * tg, j1 = 2 * tg + 1;
    const int p0 = (j0 < 4) ? 2 * j0 : 2 * j0 - 7;
    const int p1 = (j1 < 4) ? 2 * j1 : 2 * j1 - 7;
    #pragma unroll
    for (int nt = 0; nt < 8; nt++)
        #pragma unroll
        for (int r = 0; r < 2; r++) {
            int row = w * 16 + g + 8 * r;
            float* rp = Ob + (size_t)row * D_ + nt * 8;
            rp[p0] = __uint_as_float(f2tf32(o[nt][2 * r]     * inv[r]));
            rp[p1] = __uint_as_float(f2tf32(o[nt][2 * r + 1] * inv[r]));
        }
}

// ---------------------------------------------------------------------------
extern "C" void kernel_launch(void* const* d_in, const int* in_sizes, int n_in,
                              void* d_out, int out_size)
{
    (void)in_sizes; (void)n_in; (void)out_size;
    const float* q  = (const float*)d_in[0];
    const float* k  = (const float*)d_in[1];
    const float* v  = (const float*)d_in[2];
    const float* Wq = (const float*)d_in[4];
    const float* bq = (const float*)d_in[5];
    const float* Wk = (const float*)d_in[6];
    const float* bk = (const float*)d_in[7];
    const float* Wv = (const float*)d_in[8];
    const float* bv = (const float*)d_in[9];
    const float* Wo = (const float*)d_in[10];
    const float* bo = (const float*)d_in[11];
    float* out = (float*)d_out;

    const int gemm_smem = 4 * GSTAGE_ * 4;                 // 81920 B (2 stages)
    cudaFuncSetAttribute(qkv_gemm_mma, cudaFuncAttributeMaxDynamicSharedMemorySize, gemm_smem);
    cudaFuncSetAttribute(out_gemm_mma, cudaFuncAttributeMaxDynamicSharedMemorySize, gemm_smem);
    const int attn_smem = (2 * 64 * KST_ + 2 * 64 * VST_) * 4;  // 71680 B -> 3 CTA/SM
    cudaFuncSetAttribute(attn_kernel, cudaFuncAttributeMaxDynamicSharedMemorySize, attn_smem);

    // prepass: tf32-round + k-permute (bit-identical numerics)
    round_inputs_kernel<<<dim3((B_*S_*D_/8)/256, 3), 256>>>(q, k, v);
    round_weights_kernel<<<dim3((D_*D_/8)/256, 4), 256>>>(Wq, Wk, Wv, Wo);

    dim3 gqkv(1024/128, M_/128, 3);
    qkv_gemm_mma<<<gqkv, 256, gemm_smem>>>(bq, bk, bv);

    attn_kernel<<<dim3(S_/64, H_, B_), 128, attn_smem>>>();

    out_gemm_mma<<<dim3(1024/128, M_/128), 256, gemm_smem>>>(bo, out);
}